// round 1
// baseline (speedup 1.0000x reference)
#include <cuda_runtime.h>
#include <cuda_bf16.h>
#include <cstdint>

#define NN 50000
#define EE 800000
#define DD 96          // D_IN == D_OUT == 96
#define DD4 24         // 96 floats = 24 float4

// scratch: support = X @ W  (19.2 MB)
__device__ float g_support[(size_t)NN * DD];

// ---------------------------------------------------------------------------
// GEMM: support[N,96] = X[N,96] @ W[96,96]
// Block: 192 threads, 32 rows per block. Thread = 4 rows x 4 cols (float4).
// Shared: full W (36864B) + X tile (12288B) = 49152B (static limit, exact).
// ---------------------------------------------------------------------------
__global__ __launch_bounds__(192) void gemm_kernel(const float* __restrict__ x,
                                                   const float* __restrict__ w) {
    __shared__ float Ws[DD * DD];   // 96x96
    __shared__ float Xs[32 * DD];   // 32x96

    const int tid = threadIdx.x;          // 0..191
    const int row0 = blockIdx.x * 32;

    // cooperative load of W: 9216 floats = 2304 float4, 12 per thread
    {
        const float4* w4 = reinterpret_cast<const float4*>(w);
        float4* ws4 = reinterpret_cast<float4*>(Ws);
#pragma unroll
        for (int i = 0; i < 12; i++) ws4[tid + i * 192] = w4[tid + i * 192];
    }
    // cooperative load of X tile: 768 float4, 4 per thread (guard tail rows)
    {
        const float4* x4 = reinterpret_cast<const float4*>(x);
        float4* xs4 = reinterpret_cast<float4*>(Xs);
#pragma unroll
        for (int i = 0; i < 4; i++) {
            int f = tid + i * 192;            // 0..767
            int r = f / DD4;                  // 0..31
            int gr = row0 + r;
            float4 v = make_float4(0.f, 0.f, 0.f, 0.f);
            if (gr < NN) v = x4[(size_t)gr * DD4 + (f % DD4)];
            xs4[f] = v;
        }
    }
    __syncthreads();

    const int rt = tid / DD4;   // 0..7 -> rows rt*4 .. rt*4+3
    const int ct = tid % DD4;   // 0..23 -> cols ct*4 .. ct*4+3

    float acc[4][4];
#pragma unroll
    for (int i = 0; i < 4; i++)
#pragma unroll
        for (int j = 0; j < 4; j++) acc[i][j] = 0.f;

    const float4* ws4 = reinterpret_cast<const float4*>(Ws);
#pragma unroll 8
    for (int k = 0; k < DD; k++) {
        float4 wv = ws4[k * DD4 + ct];
        float xs0 = Xs[(rt * 4 + 0) * DD + k];
        float xs1 = Xs[(rt * 4 + 1) * DD + k];
        float xs2 = Xs[(rt * 4 + 2) * DD + k];
        float xs3 = Xs[(rt * 4 + 3) * DD + k];
        acc[0][0] += xs0 * wv.x; acc[0][1] += xs0 * wv.y; acc[0][2] += xs0 * wv.z; acc[0][3] += xs0 * wv.w;
        acc[1][0] += xs1 * wv.x; acc[1][1] += xs1 * wv.y; acc[1][2] += xs1 * wv.z; acc[1][3] += xs1 * wv.w;
        acc[2][0] += xs2 * wv.x; acc[2][1] += xs2 * wv.y; acc[2][2] += xs2 * wv.z; acc[2][3] += xs2 * wv.w;
        acc[3][0] += xs3 * wv.x; acc[3][1] += xs3 * wv.y; acc[3][2] += xs3 * wv.z; acc[3][3] += xs3 * wv.w;
    }

    float4* s4 = reinterpret_cast<float4*>(g_support);
#pragma unroll
    for (int i = 0; i < 4; i++) {
        int gr = row0 + rt * 4 + i;
        if (gr < NN)
            s4[(size_t)gr * DD4 + ct] = make_float4(acc[i][0], acc[i][1], acc[i][2], acc[i][3]);
    }
}

// ---------------------------------------------------------------------------
// Init out with bias: out[i][d] = b[d]
// ---------------------------------------------------------------------------
__global__ void init_kernel(float* __restrict__ out, const float* __restrict__ b) {
    int i = blockIdx.x * blockDim.x + threadIdx.x;   // float4 index
    const int total4 = NN * DD4;
    if (i >= total4) return;
    const float4* b4 = reinterpret_cast<const float4*>(b);
    reinterpret_cast<float4*>(out)[i] = b4[i % DD4];
}

// ---------------------------------------------------------------------------
// Scatter: for each edge e, out[row[e]] += val[e] * support[col[e]]
// 24 threads per edge, one float4 each, vectorized red.global.add.v4.f32
// ---------------------------------------------------------------------------
__global__ __launch_bounds__(256) void scatter_kernel(const int* __restrict__ erow,
                                                      const int* __restrict__ ecol,
                                                      const float* __restrict__ eval_,
                                                      float* __restrict__ out) {
    unsigned int t = blockIdx.x * 256u + threadIdx.x;     // < E*24 = 19.2M
    unsigned int e = t / DD4;
    unsigned int j = t - e * DD4;
    if (e >= EE) return;

    int r = erow[e];
    int c = ecol[e];
    float v = eval_[e];

    float4 s = reinterpret_cast<const float4*>(g_support)[(size_t)c * DD4 + j];
    float a0 = s.x * v, a1 = s.y * v, a2 = s.z * v, a3 = s.w * v;

    float* p = out + (size_t)r * DD + j * 4;
    asm volatile("red.global.add.v4.f32 [%0], {%1, %2, %3, %4};"
                 :: "l"(p), "f"(a0), "f"(a1), "f"(a2), "f"(a3)
                 : "memory");
}

extern "C" void kernel_launch(void* const* d_in, const int* in_sizes, int n_in,
                              void* d_out, int out_size) {
    const float* x     = (const float*)d_in[0];
    const int*   erow  = (const int*)d_in[1];
    const int*   ecol  = (const int*)d_in[2];
    const float* evalv = (const float*)d_in[3];
    const float* w     = (const float*)d_in[4];
    const float* b     = (const float*)d_in[5];
    float* out = (float*)d_out;

    // support = X @ W
    gemm_kernel<<<(NN + 31) / 32, 192>>>(x, w);
    // out = b (broadcast)
    init_kernel<<<(NN * DD4 + 255) / 256, 256>>>(out, b);
    // out += A @ support
    scatter_kernel<<<(EE * DD4) / 256, 256>>>(erow, ecol, evalv, out);
}

// round 2
// speedup vs baseline: 1.0762x; 1.0762x over previous
#include <cuda_runtime.h>
#include <cuda_bf16.h>
#include <cstdint>

#define NN 50000
#define EE 800000
#define DD 96
#define DD4 24
#define NB_SCAN 196            // ceil(50000/256)

// scratch
__device__ float g_support[(size_t)NN * DD];   // X @ W
__device__ int   g_count[NN];                  // histogram, then write-ptr
__device__ int   g_rowptr[NN + 1];
__device__ int   g_blocksums[256];
__device__ int   g_scol[EE];
__device__ float g_sval[EE];

// ---- f32x2 helpers -------------------------------------------------------
__device__ __forceinline__ void fma2(unsigned long long& d,
                                     unsigned long long a,
                                     unsigned long long b) {
    asm("fma.rn.f32x2 %0, %1, %2, %0;" : "+l"(d) : "l"(a), "l"(b));
}
__device__ __forceinline__ unsigned long long pack2(float lo, float hi) {
    unsigned long long r;
    asm("mov.b64 %0, {%1, %2};" : "=l"(r) : "f"(lo), "f"(hi));
    return r;
}

// ---------------------------------------------------------------------------
// GEMM: support[N,96] = X[N,96] @ W[96,96] with f32x2 packed FMA.
// 96 threads/block, 32 rows/block. Thread = 8 rows (4 f32x2 pairs) x 4 cols.
// smem: W (36KB) + X^T tile [96][32] (12KB) = 48KB exactly.
// ---------------------------------------------------------------------------
__global__ __launch_bounds__(96) void gemm_kernel(const float* __restrict__ x,
                                                  const float* __restrict__ w) {
    __shared__ float Ws[DD * DD];      // [k][col]
    __shared__ float Xt[DD * 32];      // [k][row]  (transposed tile)

    const int tid = threadIdx.x;       // 0..95
    const int row0 = blockIdx.x * 32;

    // load W: 2304 float4, 24 per thread
    {
        const float4* w4 = reinterpret_cast<const float4*>(w);
        float4* ws4 = reinterpret_cast<float4*>(Ws);
#pragma unroll
        for (int i = 0; i < 24; i++) ws4[tid + i * 96] = w4[tid + i * 96];
    }
    // load X tile transposed: warp w handles k4 = w + 3i, lane r = tid%32
    {
        const int r = tid & 31;
        const int wp = tid >> 5;       // 0..2
        const int gr = row0 + r;
        const float4* x4 = reinterpret_cast<const float4*>(x);
#pragma unroll
        for (int i = 0; i < 8; i++) {
            int k4 = wp + 3 * i;       // 0..23
            float4 v = make_float4(0.f, 0.f, 0.f, 0.f);
            if (gr < NN) v = x4[(size_t)gr * DD4 + k4];
            Xt[(k4 * 4 + 0) * 32 + r] = v.x;   // consecutive lanes -> no conflict
            Xt[(k4 * 4 + 1) * 32 + r] = v.y;
            Xt[(k4 * 4 + 2) * 32 + r] = v.z;
            Xt[(k4 * 4 + 3) * 32 + r] = v.w;
        }
    }
    __syncthreads();

    const int rt = tid / DD4;          // 0..3  -> rows rt*8 .. rt*8+7
    const int ct = tid % DD4;          // 0..23 -> cols ct*4 .. ct*4+3

    unsigned long long acc[4][4];      // [row-pair][col]
#pragma unroll
    for (int i = 0; i < 4; i++)
#pragma unroll
        for (int j = 0; j < 4; j++) acc[i][j] = 0ull;

    const float4* ws4 = reinterpret_cast<const float4*>(Ws);
#pragma unroll 4
    for (int k = 0; k < DD; k++) {
        // 4 packed row-pairs (LDS.64)
        const double* xp = reinterpret_cast<const double*>(Xt + k * 32 + rt * 8);
        unsigned long long x0 = __double_as_longlong(xp[0]);
        unsigned long long x1 = __double_as_longlong(xp[1]);
        unsigned long long x2 = __double_as_longlong(xp[2]);
        unsigned long long x3 = __double_as_longlong(xp[3]);
        float4 wv = ws4[k * DD4 + ct];
        unsigned long long w0 = pack2(wv.x, wv.x);
        unsigned long long w1 = pack2(wv.y, wv.y);
        unsigned long long w2 = pack2(wv.z, wv.z);
        unsigned long long w3 = pack2(wv.w, wv.w);
        fma2(acc[0][0], x0, w0); fma2(acc[0][1], x0, w1); fma2(acc[0][2], x0, w2); fma2(acc[0][3], x0, w3);
        fma2(acc[1][0], x1, w0); fma2(acc[1][1], x1, w1); fma2(acc[1][2], x1, w2); fma2(acc[1][3], x1, w3);
        fma2(acc[2][0], x2, w0); fma2(acc[2][1], x2, w1); fma2(acc[2][2], x2, w2); fma2(acc[2][3], x2, w3);
        fma2(acc[3][0], x3, w0); fma2(acc[3][1], x3, w1); fma2(acc[3][2], x3, w2); fma2(acc[3][3], x3, w3);
    }

    float4* s4 = reinterpret_cast<float4*>(g_support);
#pragma unroll
    for (int i = 0; i < 4; i++) {
        int grl = row0 + rt * 8 + 2 * i;     // low half of pair
        float4 lo, hi;
        lo.x = __uint_as_float((unsigned)(acc[i][0]));
        lo.y = __uint_as_float((unsigned)(acc[i][1]));
        lo.z = __uint_as_float((unsigned)(acc[i][2]));
        lo.w = __uint_as_float((unsigned)(acc[i][3]));
        hi.x = __uint_as_float((unsigned)(acc[i][0] >> 32));
        hi.y = __uint_as_float((unsigned)(acc[i][1] >> 32));
        hi.z = __uint_as_float((unsigned)(acc[i][2] >> 32));
        hi.w = __uint_as_float((unsigned)(acc[i][3] >> 32));
        if (grl < NN)     s4[(size_t)grl * DD4 + ct] = lo;
        if (grl + 1 < NN) s4[(size_t)(grl + 1) * DD4 + ct] = hi;
    }
}

// ---------------------------------------------------------------------------
// Counting sort of edges by row
// ---------------------------------------------------------------------------
__global__ void zero_kernel() {
    int i = blockIdx.x * 256 + threadIdx.x;
    if (i < NN) g_count[i] = 0;
}

__global__ void hist_kernel(const int* __restrict__ erow) {
    int e = blockIdx.x * 256 + threadIdx.x;
    if (e < EE) atomicAdd(&g_count[erow[e]], 1);
}

// block-level exclusive scan of 256 ints; writes partial scan + block sum
__global__ void scan1_kernel() {
    __shared__ int s[256];
    int t = threadIdx.x;
    int idx = blockIdx.x * 256 + t;
    int v = (idx < NN) ? g_count[idx] : 0;
    s[t] = v;
    __syncthreads();
#pragma unroll
    for (int off = 1; off < 256; off <<= 1) {
        int x = (t >= off) ? s[t - off] : 0;
        __syncthreads();
        s[t] += x;
        __syncthreads();
    }
    if (idx < NN) g_rowptr[idx] = s[t] - v;       // exclusive within block
    if (t == 255) g_blocksums[blockIdx.x] = s[t]; // block total
}

__global__ void scan2_kernel() {
    __shared__ int s[256];
    int t = threadIdx.x;
    int v = (t < NB_SCAN) ? g_blocksums[t] : 0;
    s[t] = v;
    __syncthreads();
#pragma unroll
    for (int off = 1; off < 256; off <<= 1) {
        int x = (t >= off) ? s[t - off] : 0;
        __syncthreads();
        s[t] += x;
        __syncthreads();
    }
    if (t < NB_SCAN) g_blocksums[t] = s[t] - v;   // exclusive
}

__global__ void fixup_kernel() {
    int idx = blockIdx.x * 256 + threadIdx.x;
    if (idx < NN) {
        int p = g_rowptr[idx] + g_blocksums[blockIdx.x];
        g_rowptr[idx] = p;
        g_count[idx] = p;                          // write pointer copy
    }
    if (idx == 0) g_rowptr[NN] = EE;
}

__global__ void build_kernel(const int* __restrict__ erow,
                             const int* __restrict__ ecol,
                             const float* __restrict__ eval_) {
    int e = blockIdx.x * 256 + threadIdx.x;
    if (e >= EE) return;
    int r = erow[e];
    int pos = atomicAdd(&g_count[r], 1);
    g_scol[pos] = ecol[e];
    g_sval[pos] = eval_[e];
}

// ---------------------------------------------------------------------------
// SpMM: one warp per row, register accumulation, bias fused, single store.
// ---------------------------------------------------------------------------
__global__ __launch_bounds__(256) void spmm_kernel(const float* __restrict__ b,
                                                   float* __restrict__ out) {
    int row = blockIdx.x * 8 + (threadIdx.x >> 5);
    if (row >= NN) return;
    int lane = threadIdx.x & 31;

    int start = g_rowptr[row];
    int end   = g_rowptr[row + 1];

    float4 acc = make_float4(0.f, 0.f, 0.f, 0.f);
    const float4* s4 = reinterpret_cast<const float4*>(g_support);

    for (int e0 = start; e0 < end; e0 += 32) {
        int n = min(32, end - e0);
        int c = 0; float v = 0.f;
        if (lane < n) { c = g_scol[e0 + lane]; v = g_sval[e0 + lane]; }
        for (int i = 0; i < n; i++) {
            int   ci = __shfl_sync(0xffffffffu, c, i);
            float vi = __shfl_sync(0xffffffffu, v, i);
            if (lane < DD4) {
                float4 s = s4[(size_t)ci * DD4 + lane];
                acc.x += vi * s.x; acc.y += vi * s.y;
                acc.z += vi * s.z; acc.w += vi * s.w;
            }
        }
    }

    if (lane < DD4) {
        float4 bb = reinterpret_cast<const float4*>(b)[lane];
        float4 r;
        r.x = acc.x + bb.x; r.y = acc.y + bb.y;
        r.z = acc.z + bb.z; r.w = acc.w + bb.w;
        reinterpret_cast<float4*>(out)[(size_t)row * DD4 + lane] = r;
    }
}

extern "C" void kernel_launch(void* const* d_in, const int* in_sizes, int n_in,
                              void* d_out, int out_size) {
    const float* x     = (const float*)d_in[0];
    const int*   erow  = (const int*)d_in[1];
    const int*   ecol  = (const int*)d_in[2];
    const float* evalv = (const float*)d_in[3];
    const float* w     = (const float*)d_in[4];
    const float* b     = (const float*)d_in[5];
    float* out = (float*)d_out;

    gemm_kernel<<<(NN + 31) / 32, 96>>>(x, w);

    zero_kernel<<<NB_SCAN, 256>>>();
    hist_kernel<<<(EE + 255) / 256, 256>>>(erow);
    scan1_kernel<<<NB_SCAN, 256>>>();
    scan2_kernel<<<1, 256>>>();
    fixup_kernel<<<NB_SCAN, 256>>>();
    build_kernel<<<(EE + 255) / 256, 256>>>(erow, ecol, evalv);

    spmm_kernel<<<(NN + 7) / 8, 256>>>(b, out);
}